// round 15
// baseline (speedup 1.0000x reference)
#include <cuda_runtime.h>
#include <cuda_fp16.h>
#include <cstdint>

#define B_    16
#define N_    3136
#define DIM   512
#define HEADS 8
#define HW    56
#define SD    256
#define S_    32
#define BN    (B_ * N_)
#define ELEMS ((long)BN * DIM)

// ---------------- scratch ----------------
__device__ __half g_x16[ELEMS];
__device__ __half g_d116[ELEMS];
__device__ __half g_a316[ELEMS];
__device__ __half g_q16[ELEMS];
__device__ __half g_w16[3][DIM * DIM];
__device__ float g_half[B_][32][N_];
__device__ float g_k[2 * B_ * HEADS * 49 * S_];
__device__ float g_v[2 * B_ * HEADS * 49 * S_];

// ---------------- helpers ----------------
__device__ __forceinline__ uint32_t smem_u32(const void* p) {
    uint32_t a;
    asm("{ .reg .u64 t; cvta.to.shared.u64 t, %1; cvt.u32.u64 %0, t; }" : "=r"(a) : "l"(p));
    return a;
}
__device__ __forceinline__ void cp16(uint32_t d, const void* g) {
    asm volatile("cp.async.cg.shared.global [%0], [%1], 16;" :: "r"(d), "l"(g));
}
#define CP_COMMIT() asm volatile("cp.async.commit_group;" ::: "memory")
#define CP_WAIT(n)  asm volatile("cp.async.wait_group %0;" :: "n"(n) : "memory")

#define LDSM_X4(r, a) \
    asm volatile("ldmatrix.sync.aligned.m8n8.x4.shared.b16 {%0,%1,%2,%3}, [%4];" \
        : "=r"((r)[0]), "=r"((r)[1]), "=r"((r)[2]), "=r"((r)[3]) : "r"(a))
#define LDSM_X2(r, a) \
    asm volatile("ldmatrix.sync.aligned.m8n8.x2.shared.b16 {%0,%1}, [%2];" \
        : "=r"((r)[0]), "=r"((r)[1]) : "r"(a))
#define MMA16816F16(c, a, b) \
    asm volatile("mma.sync.aligned.m16n8k16.row.col.f32.f16.f16.f32 " \
        "{%0,%1,%2,%3},{%4,%5,%6,%7},{%8,%9},{%0,%1,%2,%3};" \
        : "+f"((c)[0]), "+f"((c)[1]), "+f"((c)[2]), "+f"((c)[3]) \
        : "r"((a)[0]), "r"((a)[1]), "r"((a)[2]), "r"((a)[3]), "r"((b)[0]), "r"((b)[1]))

#define FMA2(acc, a, b) \
    asm("fma.rn.f32x2 %0, %1, %2, %0;" : "+l"(acc) : "l"(a), "l"(b))
#define PACK2(d, x, y)  asm("mov.b64 %0, {%1,%2};" : "=l"(d) : "f"(x), "f"(y))
#define UNPACK2(x, y, d) asm("mov.b64 {%0,%1}, %2;" : "=f"(x), "=f"(y) : "l"(d))

__device__ __forceinline__ void store_h4(float4 v, __half* dst) {
    __half2* d = (__half2*)dst;
    d[0] = __floats2half2_rn(v.x, v.y);
    d[1] = __floats2half2_rn(v.z, v.w);
}

// ---------------- weight conversion ----------------
__global__ void wsplit3_kernel(const float* __restrict__ s0, const float* __restrict__ s1,
                               const float* __restrict__ s2, __half* __restrict__ out) {
    int w = blockIdx.y;
    const float* src = w == 0 ? s0 : (w == 1 ? s1 : s2);
    long i = (long)blockIdx.x * blockDim.x + threadIdx.x;
    float4 v = ((const float4*)src)[i];
    store_h4(v, out + (long)w * DIM * DIM + i * 4);
}

// ---------------- 3x3 depthwise conv + fused x convert ----------------
__global__ void __launch_bounds__(128)
dwconv_kernel(const float* __restrict__ x, const float* __restrict__ w,
              const float* __restrict__ bias,
              __half* __restrict__ o16, __half* __restrict__ x16) {
    int p0 = blockIdx.x * 8;
    int c4 = threadIdx.x * 4;
    float wr[9][4];
    #pragma unroll
    for (int t = 0; t < 9; t++)
        #pragma unroll
        for (int cc = 0; cc < 4; cc++) wr[t][cc] = w[(c4 + cc) * 9 + t];
    float4 b4 = *(const float4*)(bias + c4);

    #pragma unroll
    for (int pp = 0; pp < 8; pp++) {
        int p = p0 + pp;
        int b = p / N_, pix = p - b * N_;
        int hy = pix / HW, hx = pix - hy * HW;
        float4 acc = b4, xc = make_float4(0.f, 0.f, 0.f, 0.f);
        #pragma unroll
        for (int dy = 0; dy < 3; dy++) {
            int yy = hy + dy - 1;
            if (yy < 0 || yy >= HW) continue;
            #pragma unroll
            for (int dx = 0; dx < 3; dx++) {
                int xx = hx + dx - 1;
                if (xx < 0 || xx >= HW) continue;
                float4 v = *(const float4*)(x + ((long)b * N_ + yy * HW + xx) * DIM + c4);
                if (dy == 1 && dx == 1) xc = v;
                int t = dy * 3 + dx;
                acc.x += wr[t][0] * v.x; acc.y += wr[t][1] * v.y;
                acc.z += wr[t][2] * v.z; acc.w += wr[t][3] * v.w;
            }
        }
        long off = (long)p * DIM + c4;
        store_h4(acc, o16 + off);
        store_h4(xc,  x16 + off);
    }
}

// ---------------------------------------------------------------------------
// fp16 mma.sync GEMM — tile 128x256, 512 threads (16 warps, warp 64x32),
// 2-stage cp.async. Epilogue modes: 0 fp32(+bias), 1 fp16, 2 group sums.
// ---------------------------------------------------------------------------
#define STAGE_B  30720           // A 128x80B (10240) + W 256x80B (20480)
#define GSMEM    (2 * STAGE_B)

struct GemmArgs {
    const __half *A, *W;
    const float* bias;
    float* C;
    __half* C16;
    int mode;
};

__global__ void __launch_bounds__(512, 1)
gemm_dual(GemmArgs a0, GemmArgs a1) {
    const GemmArgs& g = blockIdx.z ? a1 : a0;
    const __half* __restrict__ A = g.A;
    const __half* __restrict__ W = g.W;
    const float* bias = g.bias;

    extern __shared__ char smem[];
    uint32_t sb = smem_u32(smem);
    const int tid = threadIdx.x, lane = tid & 31, wid = tid >> 5;
    const int wm = wid & 1, wn = wid >> 1;          // 2 x 8 warp grid
    const long m0 = (long)blockIdx.x * 128;
    const int n0 = blockIdx.y * 256;

    auto load_chunk = [&](int ck, int st) {
        uint32_t base = sb + st * STAGE_B;
        // A: 512 segs (128 rows x 4), W: 1024 segs (256 rows x 4); 3 per thread
        {
            int r = tid >> 2, seg = tid & 3;
            cp16(base + r * 80 + seg * 16, A + (m0 + r) * DIM + ck * 32 + seg * 8);
        }
        #pragma unroll
        for (int it = 0; it < 2; it++) {
            int loc = tid + it * 512;               // 0..1023
            int r = loc >> 2, seg = loc & 3;
            cp16(base + 10240 + r * 80 + seg * 16,
                 W + (long)(n0 + r) * DIM + ck * 32 + seg * 8);
        }
        CP_COMMIT();
    };

    float acc[4][4][4];
    #pragma unroll
    for (int i = 0; i < 4; i++)
        #pragma unroll
        for (int j = 0; j < 4; j++)
            #pragma unroll
            for (int r = 0; r < 4; r++) acc[i][j][r] = 0.f;

    load_chunk(0, 0);

    const int arow = lane & 15;
    const int acolB = (lane >> 4) ? 16 : 0;
    const int brow = lane & 7;
    const int bcolB = ((lane >> 3) & 1) ? 16 : 0;

    for (int c = 0; c < 16; c++) {
        if (c + 1 < 16) { load_chunk(c + 1, (c + 1) & 1); CP_WAIT(1); }
        else            { CP_WAIT(0); }
        __syncthreads();
        uint32_t base = sb + (c & 1) * STAGE_B;
        #pragma unroll
        for (int ks = 0; ks < 2; ks++) {
            const int kb = ks * 32;
            uint32_t ah[4][4];
            #pragma unroll
            for (int i = 0; i < 4; i++) {
                uint32_t addr = base + (wm * 64 + i * 16 + arow) * 80 + kb + acolB;
                LDSM_X4(ah[i], addr);
            }
            #pragma unroll
            for (int j = 0; j < 4; j++) {
                uint32_t baddr = base + 10240 + (wn * 32 + j * 8 + brow) * 80 + kb + bcolB;
                uint32_t wh2[2];
                LDSM_X2(wh2, baddr);
                #pragma unroll
                for (int i = 0; i < 4; i++)
                    MMA16816F16(acc[i][j], ah[i], wh2);
            }
        }
        __syncthreads();
    }

    if (g.mode == 2) {
        #pragma unroll
        for (int i = 0; i < 4; i++) {
            float gA0 = 0.f, gA8 = 0.f, gB0 = 0.f, gB8 = 0.f;
            #pragma unroll
            for (int j = 0; j < 4; j++) {
                int col = n0 + wn * 32 + j * 8 + (lane & 3) * 2;
                float b0 = bias[col], b1 = bias[col + 1];
                float s0 = acc[i][j][0] + b0 + acc[i][j][1] + b1;
                float s8 = acc[i][j][2] + b0 + acc[i][j][3] + b1;
                if (j < 2) { gA0 += s0; gA8 += s8; }
                else       { gB0 += s0; gB8 += s8; }
            }
            #pragma unroll
            for (int d = 1; d <= 2; d <<= 1) {
                gA0 += __shfl_xor_sync(0xffffffffu, gA0, d);
                gA8 += __shfl_xor_sync(0xffffffffu, gA8, d);
                gB0 += __shfl_xor_sync(0xffffffffu, gB0, d);
                gB8 += __shfl_xor_sync(0xffffffffu, gB8, d);
            }
            if ((lane & 3) == 0) {
                int g0 = (n0 + wn * 32) >> 4, g1 = g0 + 1;
                long m = m0 + wm * 64 + i * 16 + (lane >> 2);
                int bb = (int)(m / N_), pix = (int)(m - (long)bb * N_);
                g_half[bb][g0][pix] = gA0;
                g_half[bb][g1][pix] = gB0;
                m += 8; bb = (int)(m / N_); pix = (int)(m - (long)bb * N_);
                g_half[bb][g0][pix] = gA8;
                g_half[bb][g1][pix] = gB8;
            }
        }
    } else if (g.mode == 1) {
        __half* C16 = g.C16;
        #pragma unroll
        for (int i = 0; i < 4; i++) {
            long r0 = m0 + wm * 64 + i * 16 + (lane >> 2);
            #pragma unroll
            for (int j = 0; j < 4; j++) {
                int col = n0 + wn * 32 + j * 8 + (lane & 3) * 2;
                *(__half2*)(C16 + r0 * DIM + col) =
                    __floats2half2_rn(acc[i][j][0], acc[i][j][1]);
                *(__half2*)(C16 + (r0 + 8) * DIM + col) =
                    __floats2half2_rn(acc[i][j][2], acc[i][j][3]);
            }
        }
    } else {
        float* C = g.C;
        #pragma unroll
        for (int i = 0; i < 4; i++) {
            long r0 = m0 + wm * 64 + i * 16 + (lane >> 2);
            #pragma unroll
            for (int j = 0; j < 4; j++) {
                int col = n0 + wn * 32 + j * 8 + (lane & 3) * 2;
                float b0 = bias ? bias[col] : 0.f, b1 = bias ? bias[col + 1] : 0.f;
                float2 v0 = { acc[i][j][0] + b0, acc[i][j][1] + b1 };
                float2 v1 = { acc[i][j][2] + b0, acc[i][j][3] + b1 };
                *(float2*)(C + r0 * DIM + col) = v0;
                *(float2*)(C + (r0 + 8) * DIM + col) = v1;
            }
        }
    }
}

// ---------------- prep ----------------
__global__ void prep_kernel(const float* __restrict__ fc0, const float* __restrict__ fc1,
                            const float* __restrict__ sg0, const float* __restrict__ sg1,
                            const float* __restrict__ lw0, const float* __restrict__ lb0,
                            const float* __restrict__ lw1, const float* __restrict__ lb1) {
    int blk = blockIdx.x;
    int br = blk >> 7, bh = blk & 127, b = bh >> 3, h = bh & 7;
    int tid = threadIdx.x;
    __shared__ float pooled[49][32], tmp[49][32], vsh[49][33];

    for (int idx = tid; idx < 49*32; idx += 256) {
        int w = idx >> 5, s = idx & 31;
        int ky = w / 7, kx = w - ky * 7;
        float sum;
        if (br == 0) {
            int ll0 = 2*s, ll1 = 2*s + 1;
            int p0 = ((ll0>>3)*7 + ky)*HW + (ll0&7)*7 + kx;
            int p1 = ((ll1>>3)*7 + ky)*HW + (ll1&7)*7 + kx;
            sum = (g_half[b][2*h][p0] + g_half[b][2*h+1][p0]
                 + g_half[b][2*h][p1] + g_half[b][2*h+1][p1]) * (1.f/64.f);
        } else {
            int ll = s >> 1;
            int p = ((ll>>2)*13 + ky*2)*HW + (ll&3)*13 + kx*2;
            sum = g_half[b][16 + 2*h + (s&1)][p] * (1.f/16.f);
        }
        pooled[w][s] = sum;
    }
    __syncthreads();
    const float* fc = br ? fc1 : fc0;
    for (int idx = tid; idx < 49*32; idx += 256) {
        int w = idx >> 5, t = idx & 31;
        float sum = 0.f;
        #pragma unroll
        for (int s = 0; s < 32; s++) sum += pooled[w][s] * fc[t*32+s];
        tmp[w][t] = sum;
    }
    __syncthreads();
    const float* sg = br ? sg1 : sg0;
    const float kscale = 0.17677669529663689f;
    for (int idx = tid; idx < 49*64; idx += 256) {
        int w = idx >> 6, j = idx & 63;
        float sum = 0.f;
        #pragma unroll
        for (int t = 0; t < 32; t++) sum += tmp[w][t] * sg[j*32+t];
        if (j < 32) g_k[(long)blk*1568 + w*32 + j] = sum * kscale;
        else        vsh[w][j-32] = sum;
    }
    __syncthreads();
    const float* lw = br ? lw1 : lw0;
    const float* lb = br ? lb1 : lb0;
    for (int idx = tid; idx < 49*32; idx += 256) {
        int w = idx >> 5, s = idx & 31;
        int wy = w / 7, wx = w - wy * 7, ch = h*S_ + s;
        float acc = vsh[w][s] + lb[ch];
        #pragma unroll
        for (int dy = 0; dy < 3; dy++) {
            int yy = wy + dy - 1;
            if (yy < 0 || yy >= 7) continue;
            #pragma unroll
            for (int dx = 0; dx < 3; dx++) {
                int xx = wx + dx - 1;
                if (xx < 0 || xx >= 7) continue;
                acc += lw[ch*9 + dy*3 + dx] * vsh[yy*7+xx][s];
            }
        }
        g_v[(long)blk*1568 + w*32 + s] = acc;
    }
}

// ---------------- attention: fp16 q, packed f32x2 FMA ----------------
__global__ void __launch_bounds__(256)
attn_kernel(const __half* __restrict__ q, __half* __restrict__ a16) {
    int blk = blockIdx.x;
    int br = blk >> 7, bh = blk & 127, b = bh >> 3, h = bh & 7;
    int tid = threadIdx.x;
    __shared__ float ksh[49][32], vsh[49][32], osh[256][33];
    const float* kp = g_k + (long)blk * 1568;
    const float* vp = g_v + (long)blk * 1568;
    for (int idx = tid; idx < 1568; idx += 256) { ((float*)ksh)[idx] = kp[idx]; ((float*)vsh)[idx] = vp[idx]; }
    __syncthreads();

    int n0 = blockIdx.y * 256, n = n0 + tid;
    if (n < N_) {
        const __half* qp = q + ((long)b*N_ + n)*DIM + h*64 + br*32;
        uint64_t q2[16];
        #pragma unroll
        for (int v = 0; v < 4; v++) {
            uint4 t = *(const uint4*)(qp + v*8);
            const __half2* hp = (const __half2*)&t;
            #pragma unroll
            for (int k2 = 0; k2 < 4; k2++) {
                float2 f = __half22float2(hp[k2]);
                PACK2(q2[v*4 + k2], f.x, f.y);
            }
        }
        float p[49], m = -1e30f;
        #pragma unroll
        for (int j = 0; j < 49; j++) {
            uint64_t acc2 = 0;
            #pragma unroll
            for (int d = 0; d < 8; d++) {
                ulonglong2 kk = *(const ulonglong2*)&ksh[j][d*4];
                FMA2(acc2, q2[d*2], kk.x);
                FMA2(acc2, q2[d*2+1], kk.y);
            }
            float lo, hi; UNPACK2(lo, hi, acc2);
            p[j] = lo + hi; m = fmaxf(m, p[j]);
        }
        float sum = 0.f;
        #pragma unroll
        for (int j = 0; j < 49; j++) { p[j] = __expf(p[j] - m); sum += p[j]; }
        float inv = 1.f / sum;
        uint64_t o2[16];
        #pragma unroll
        for (int d = 0; d < 16; d++) o2[d] = 0;
        #pragma unroll
        for (int j = 0; j < 49; j++) {
            uint64_t pj2; PACK2(pj2, p[j], p[j]);
            #pragma unroll
            for (int d = 0; d < 8; d++) {
                ulonglong2 vv = *(const ulonglong2*)&vsh[j][d*4];
                FMA2(o2[d*2], pj2, vv.x);
                FMA2(o2[d*2+1], pj2, vv.y);
            }
        }
        #pragma unroll
        for (int d = 0; d < 16; d++) {
            float lo, hi; UNPACK2(lo, hi, o2[d]);
            osh[tid][d*2]   = lo * inv;
            osh[tid][d*2+1] = hi * inv;
        }
    }
    __syncthreads();
    int off = br * SD + h * S_;
    for (int idx = tid; idx < 256*16; idx += 256) {
        int qq = idx >> 4, dp = (idx & 15) * 2;
        int nn = n0 + qq;
        if (nn < N_) {
            long o = ((long)b*N_ + nn)*DIM + off + dp;
            *(__half2*)(a16 + o) = __floats2half2_rn(osh[qq][dp], osh[qq][dp+1]);
        }
    }
}

// ---------------- launch ----------------
extern "C" void kernel_launch(void* const* d_in, const int* in_sizes, int n_in,
                              void* d_out, int out_size) {
    const float* x       = (const float*)d_in[0];
    const float* q_w     = (const float*)d_in[3];
    const float* kv_dw_w = (const float*)d_in[4];
    const float* kv_dw_b = (const float*)d_in[5];
    const float* kv_pw_w = (const float*)d_in[6];
    const float* kv_pw_b = (const float*)d_in[7];
    const float* fc_w0   = (const float*)d_in[8];
    const float* fc_w1   = (const float*)d_in[9];
    const float* sg_w0   = (const float*)d_in[10];
    const float* sg_w1   = (const float*)d_in[11];
    const float* lw0     = (const float*)d_in[12];
    const float* lb0     = (const float*)d_in[13];
    const float* lw1     = (const float*)d_in[14];
    const float* lb1     = (const float*)d_in[15];
    const float* proj_w  = (const float*)d_in[16];
    const float* proj_b  = (const float*)d_in[17];
    float* out = (float*)d_out;

    __half *x16, *d116, *a316, *q16, *w16;
    cudaGetSymbolAddress((void**)&x16, g_x16);
    cudaGetSymbolAddress((void**)&d116, g_d116);
    cudaGetSymbolAddress((void**)&a316, g_a316);
    cudaGetSymbolAddress((void**)&q16, g_q16);
    cudaGetSymbolAddress((void**)&w16, g_w16);

    cudaFuncSetAttribute(gemm_dual, cudaFuncAttributeMaxDynamicSharedMemorySize, GSMEM);

    wsplit3_kernel<<<dim3(DIM*DIM/4/256, 3), 256>>>(q_w, kv_pw_w, proj_w, w16);
    dwconv_kernel<<<BN/8, 128>>>(x, kv_dw_w, kv_dw_b, d116, x16);

    GemmArgs kvA { d116, w16 + DIM*DIM,   kv_pw_b, nullptr, nullptr, 2 };
    GemmArgs qA  { x16,  w16,             nullptr, nullptr, q16,     1 };
    GemmArgs pA  { a316, w16 + 2*DIM*DIM, proj_b,  out,     nullptr, 0 };

    gemm_dual<<<dim3(BN/128, DIM/256, 2), 512, GSMEM>>>(kvA, qA);
    prep_kernel<<<256, 256>>>(fc_w0, fc_w1, sg_w0, sg_w1, lw0, lb0, lw1, lb1);
    attn_kernel<<<dim3(256, (N_+255)/256), 256>>>(q16, a316);
    gemm_dual<<<dim3(BN/128, DIM/256, 1), 512, GSMEM>>>(pA, pA);
}

// round 16
// speedup vs baseline: 1.1921x; 1.1921x over previous
#include <cuda_runtime.h>
#include <cuda_fp16.h>
#include <cstdint>

#define B_    16
#define N_    3136
#define DIM   512
#define HEADS 8
#define HW    56
#define SD    256
#define S_    32
#define BN    (B_ * N_)
#define ELEMS ((long)BN * DIM)

// ---------------- scratch ----------------
__device__ __half g_x16[ELEMS];
__device__ __half g_d116[ELEMS];
__device__ __half g_a316[ELEMS];
__device__ __half g_q16[ELEMS];
__device__ __half g_w16[3][DIM * DIM];
__device__ float g_half[B_][32][N_];
__device__ float g_k[2 * B_ * HEADS * 49 * S_];
__device__ float g_v[2 * B_ * HEADS * 49 * S_];

// ---------------- helpers ----------------
__device__ __forceinline__ uint32_t smem_u32(const void* p) {
    uint32_t a;
    asm("{ .reg .u64 t; cvta.to.shared.u64 t, %1; cvt.u32.u64 %0, t; }" : "=r"(a) : "l"(p));
    return a;
}
__device__ __forceinline__ void cp16(uint32_t d, const void* g) {
    asm volatile("cp.async.cg.shared.global [%0], [%1], 16;" :: "r"(d), "l"(g));
}
#define CP_COMMIT() asm volatile("cp.async.commit_group;" ::: "memory")
#define CP_WAIT(n)  asm volatile("cp.async.wait_group %0;" :: "n"(n) : "memory")

#define LDSM_X4(r, a) \
    asm volatile("ldmatrix.sync.aligned.m8n8.x4.shared.b16 {%0,%1,%2,%3}, [%4];" \
        : "=r"((r)[0]), "=r"((r)[1]), "=r"((r)[2]), "=r"((r)[3]) : "r"(a))
#define MMA16816F16(c, a, b) \
    asm volatile("mma.sync.aligned.m16n8k16.row.col.f32.f16.f16.f32 " \
        "{%0,%1,%2,%3},{%4,%5,%6,%7},{%8,%9},{%0,%1,%2,%3};" \
        : "+f"((c)[0]), "+f"((c)[1]), "+f"((c)[2]), "+f"((c)[3]) \
        : "r"((a)[0]), "r"((a)[1]), "r"((a)[2]), "r"((a)[3]), "r"((b)[0]), "r"((b)[1]))

#define FMA2(acc, a, b) \
    asm("fma.rn.f32x2 %0, %1, %2, %0;" : "+l"(acc) : "l"(a), "l"(b))
#define PACK2(d, x, y)  asm("mov.b64 %0, {%1,%2};" : "=l"(d) : "f"(x), "f"(y))
#define UNPACK2(x, y, d) asm("mov.b64 {%0,%1}, %2;" : "=f"(x), "=f"(y) : "l"(d))

__device__ __forceinline__ void store_h4(float4 v, __half* dst) {
    __half2* d = (__half2*)dst;
    d[0] = __floats2half2_rn(v.x, v.y);
    d[1] = __floats2half2_rn(v.z, v.w);
}

// ---------------- weight conversion ----------------
__global__ void wsplit3_kernel(const float* __restrict__ s0, const float* __restrict__ s1,
                               const float* __restrict__ s2, __half* __restrict__ out) {
    int w = blockIdx.y;
    const float* src = w == 0 ? s0 : (w == 1 ? s1 : s2);
    long i = (long)blockIdx.x * blockDim.x + threadIdx.x;
    float4 v = ((const float4*)src)[i];
    store_h4(v, out + (long)w * DIM * DIM + i * 4);
}

// ---------------- 3x3 depthwise conv + fused x convert ----------------
__global__ void __launch_bounds__(128)
dwconv_kernel(const float* __restrict__ x, const float* __restrict__ w,
              const float* __restrict__ bias,
              __half* __restrict__ o16, __half* __restrict__ x16) {
    int p0 = blockIdx.x * 8;
    int c4 = threadIdx.x * 4;
    float wr[9][4];
    #pragma unroll
    for (int t = 0; t < 9; t++)
        #pragma unroll
        for (int cc = 0; cc < 4; cc++) wr[t][cc] = w[(c4 + cc) * 9 + t];
    float4 b4 = *(const float4*)(bias + c4);

    #pragma unroll
    for (int pp = 0; pp < 8; pp++) {
        int p = p0 + pp;
        int b = p / N_, pix = p - b * N_;
        int hy = pix / HW, hx = pix - hy * HW;
        float4 acc = b4, xc = make_float4(0.f, 0.f, 0.f, 0.f);
        #pragma unroll
        for (int dy = 0; dy < 3; dy++) {
            int yy = hy + dy - 1;
            if (yy < 0 || yy >= HW) continue;
            #pragma unroll
            for (int dx = 0; dx < 3; dx++) {
                int xx = hx + dx - 1;
                if (xx < 0 || xx >= HW) continue;
                float4 v = *(const float4*)(x + ((long)b * N_ + yy * HW + xx) * DIM + c4);
                if (dy == 1 && dx == 1) xc = v;
                int t = dy * 3 + dx;
                acc.x += wr[t][0] * v.x; acc.y += wr[t][1] * v.y;
                acc.z += wr[t][2] * v.z; acc.w += wr[t][3] * v.w;
            }
        }
        long off = (long)p * DIM + c4;
        store_h4(acc, o16 + off);
        store_h4(xc,  x16 + off);
    }
}

// ---------------------------------------------------------------------------
// fp16 mma.sync GEMM — tile 128x128, 256 thr, 2 CTA/SM, K-chunk 64 (8 chunks),
// 2-stage cp.async, ldmatrix.x4 for both A and B.
// Row stride 144B (64 halves + 8 pad): rows hit banks r*4 mod 32 -> conflict-free.
// ---------------------------------------------------------------------------
#define STAGE_B  36864            // A 128x144 + W 128x144
#define GSMEM    (2 * STAGE_B)

struct GemmArgs {
    const __half *A, *W;
    const float* bias;
    float* C;
    __half* C16;
    int mode;
};

__global__ void __launch_bounds__(256, 2)
gemm_dual(GemmArgs a0, GemmArgs a1) {
    const GemmArgs& g = blockIdx.z ? a1 : a0;
    const __half* __restrict__ A = g.A;
    const __half* __restrict__ W = g.W;
    const float* bias = g.bias;

    extern __shared__ char smem[];
    uint32_t sb = smem_u32(smem);
    const int tid = threadIdx.x, lane = tid & 31, wid = tid >> 5;
    const int wm = wid & 1, wn = wid >> 1;
    const long m0 = (long)blockIdx.x * 128;
    const int n0 = blockIdx.y * 128;

    auto load_chunk = [&](int ck, int st) {
        uint32_t base = sb + st * STAGE_B;
        #pragma unroll
        for (int it = 0; it < 8; it++) {
            int idx = tid + it * 256;       // 0..2047
            int arr = idx >> 10;            // 0:A 1:W
            int loc = idx & 1023;
            int r = loc >> 3, seg = loc & 7;
            const __half* gp = arr == 0
                ? A + (m0 + r) * DIM + ck * 64 + seg * 8
                : W + (long)(n0 + r) * DIM + ck * 64 + seg * 8;
            cp16(base + arr * 18432 + r * 144 + seg * 16, gp);
        }
        CP_COMMIT();
    };

    float acc[4][4][4];
    #pragma unroll
    for (int i = 0; i < 4; i++)
        #pragma unroll
        for (int j = 0; j < 4; j++)
            #pragma unroll
            for (int r = 0; r < 4; r++) acc[i][j][r] = 0.f;

    load_chunk(0, 0);

    // A ldmatrix.x4: lanes 0-15 rows, 16-31 rows +16B (k8-15)
    const int arow = lane & 15;
    const int acolB = (lane >> 4) ? 16 : 0;
    // B ldmatrix.x4 (2 n8-tiles): lanes 0-7 tile-even rows, 8-15 +16B,
    // 16-23 tile-odd rows, 24-31 tile-odd +16B
    const int brow8 = (lane & 7) + (((lane >> 4) & 1) << 3);  // row within 16-row pair
    const int bcolB = ((lane >> 3) & 1) ? 16 : 0;

    for (int c = 0; c < 8; c++) {
        if (c + 1 < 8) { load_chunk(c + 1, (c + 1) & 1); CP_WAIT(1); }
        else           { CP_WAIT(0); }
        __syncthreads();
        uint32_t base = sb + (c & 1) * STAGE_B;
        #pragma unroll
        for (int ks = 0; ks < 4; ks++) {
            const int kb = ks * 32;         // 16 halves = 32B per k-step
            uint32_t ah[4][4];
            #pragma unroll
            for (int i = 0; i < 4; i++) {
                uint32_t addr = base + (wm * 64 + i * 16 + arow) * 144 + kb + acolB;
                LDSM_X4(ah[i], addr);
            }
            #pragma unroll
            for (int jj = 0; jj < 2; jj++) {
                uint32_t baddr = base + 18432
                    + (wn * 32 + jj * 16 + brow8) * 144 + kb + bcolB;
                uint32_t bw[4];
                LDSM_X4(bw, baddr);          // bw[0..1]=tile 2jj, bw[2..3]=tile 2jj+1
                #pragma unroll
                for (int i = 0; i < 4; i++) {
                    MMA16816F16(acc[i][2*jj],   ah[i], bw);
                    MMA16816F16(acc[i][2*jj+1], ah[i], bw + 2);
                }
            }
        }
        __syncthreads();
    }

    if (g.mode == 2) {
        #pragma unroll
        for (int i = 0; i < 4; i++) {
            float gA0 = 0.f, gA8 = 0.f, gB0 = 0.f, gB8 = 0.f;
            #pragma unroll
            for (int j = 0; j < 4; j++) {
                int col = n0 + wn * 32 + j * 8 + (lane & 3) * 2;
                float b0 = bias[col], b1 = bias[col + 1];
                float s0 = acc[i][j][0] + b0 + acc[i][j][1] + b1;
                float s8 = acc[i][j][2] + b0 + acc[i][j][3] + b1;
                if (j < 2) { gA0 += s0; gA8 += s8; }
                else       { gB0 += s0; gB8 += s8; }
            }
            #pragma unroll
            for (int d = 1; d <= 2; d <<= 1) {
                gA0 += __shfl_xor_sync(0xffffffffu, gA0, d);
                gA8 += __shfl_xor_sync(0xffffffffu, gA8, d);
                gB0 += __shfl_xor_sync(0xffffffffu, gB0, d);
                gB8 += __shfl_xor_sync(0xffffffffu, gB8, d);
            }
            if ((lane & 3) == 0) {
                int g0 = (n0 + wn * 32) >> 4, g1 = g0 + 1;
                long m = m0 + wm * 64 + i * 16 + (lane >> 2);
                int bb = (int)(m / N_), pix = (int)(m - (long)bb * N_);
                g_half[bb][g0][pix] = gA0;
                g_half[bb][g1][pix] = gB0;
                m += 8; bb = (int)(m / N_); pix = (int)(m - (long)bb * N_);
                g_half[bb][g0][pix] = gA8;
                g_half[bb][g1][pix] = gB8;
            }
        }
    } else if (g.mode == 1) {
        __half* C16 = g.C16;
        #pragma unroll
        for (int i = 0; i < 4; i++) {
            long r0 = m0 + wm * 64 + i * 16 + (lane >> 2);
            #pragma unroll
            for (int j = 0; j < 4; j++) {
                int col = n0 + wn * 32 + j * 8 + (lane & 3) * 2;
                *(__half2*)(C16 + r0 * DIM + col) =
                    __floats2half2_rn(acc[i][j][0], acc[i][j][1]);
                *(__half2*)(C16 + (r0 + 8) * DIM + col) =
                    __floats2half2_rn(acc[i][j][2], acc[i][j][3]);
            }
        }
    } else {
        float* C = g.C;
        #pragma unroll
        for (int i = 0; i < 4; i++) {
            long r0 = m0 + wm * 64 + i * 16 + (lane >> 2);
            #pragma unroll
            for (int j = 0; j < 4; j++) {
                int col = n0 + wn * 32 + j * 8 + (lane & 3) * 2;
                float b0 = bias ? bias[col] : 0.f, b1 = bias ? bias[col + 1] : 0.f;
                float2 v0 = { acc[i][j][0] + b0, acc[i][j][1] + b1 };
                float2 v1 = { acc[i][j][2] + b0, acc[i][j][3] + b1 };
                *(float2*)(C + r0 * DIM + col) = v0;
                *(float2*)(C + (r0 + 8) * DIM + col) = v1;
            }
        }
    }
}

// ---------------- prep ----------------
__global__ void prep_kernel(const float* __restrict__ fc0, const float* __restrict__ fc1,
                            const float* __restrict__ sg0, const float* __restrict__ sg1,
                            const float* __restrict__ lw0, const float* __restrict__ lb0,
                            const float* __restrict__ lw1, const float* __restrict__ lb1) {
    int blk = blockIdx.x;
    int br = blk >> 7, bh = blk & 127, b = bh >> 3, h = bh & 7;
    int tid = threadIdx.x;
    __shared__ float pooled[49][32], tmp[49][32], vsh[49][33];

    for (int idx = tid; idx < 49*32; idx += 256) {
        int w = idx >> 5, s = idx & 31;
        int ky = w / 7, kx = w - ky * 7;
        float sum;
        if (br == 0) {
            int ll0 = 2*s, ll1 = 2*s + 1;
            int p0 = ((ll0>>3)*7 + ky)*HW + (ll0&7)*7 + kx;
            int p1 = ((ll1>>3)*7 + ky)*HW + (ll1&7)*7 + kx;
            sum = (g_half[b][2*h][p0] + g_half[b][2*h+1][p0]
                 + g_half[b][2*h][p1] + g_half[b][2*h+1][p1]) * (1.f/64.f);
        } else {
            int ll = s >> 1;
            int p = ((ll>>2)*13 + ky*2)*HW + (ll&3)*13 + kx*2;
            sum = g_half[b][16 + 2*h + (s&1)][p] * (1.f/16.f);
        }
        pooled[w][s] = sum;
    }
    __syncthreads();
    const float* fc = br ? fc1 : fc0;
    for (int idx = tid; idx < 49*32; idx += 256) {
        int w = idx >> 5, t = idx & 31;
        float sum = 0.f;
        #pragma unroll
        for (int s = 0; s < 32; s++) sum += pooled[w][s] * fc[t*32+s];
        tmp[w][t] = sum;
    }
    __syncthreads();
    const float* sg = br ? sg1 : sg0;
    const float kscale = 0.17677669529663689f;
    for (int idx = tid; idx < 49*64; idx += 256) {
        int w = idx >> 6, j = idx & 63;
        float sum = 0.f;
        #pragma unroll
        for (int t = 0; t < 32; t++) sum += tmp[w][t] * sg[j*32+t];
        if (j < 32) g_k[(long)blk*1568 + w*32 + j] = sum * kscale;
        else        vsh[w][j-32] = sum;
    }
    __syncthreads();
    const float* lw = br ? lw1 : lw0;
    const float* lb = br ? lb1 : lb0;
    for (int idx = tid; idx < 49*32; idx += 256) {
        int w = idx >> 5, s = idx & 31;
        int wy = w / 7, wx = w - wy * 7, ch = h*S_ + s;
        float acc = vsh[w][s] + lb[ch];
        #pragma unroll
        for (int dy = 0; dy < 3; dy++) {
            int yy = wy + dy - 1;
            if (yy < 0 || yy >= 7) continue;
            #pragma unroll
            for (int dx = 0; dx < 3; dx++) {
                int xx = wx + dx - 1;
                if (xx < 0 || xx >= 7) continue;
                acc += lw[ch*9 + dy*3 + dx] * vsh[yy*7+xx][s];
            }
        }
        g_v[(long)blk*1568 + w*32 + s] = acc;
    }
}

// ---------------- attention: fp16 q, packed f32x2 FMA ----------------
__global__ void __launch_bounds__(256)
attn_kernel(const __half* __restrict__ q, __half* __restrict__ a16) {
    int blk = blockIdx.x;
    int br = blk >> 7, bh = blk & 127, b = bh >> 3, h = bh & 7;
    int tid = threadIdx.x;
    __shared__ float ksh[49][32], vsh[49][32], osh[256][33];
    const float* kp = g_k + (long)blk * 1568;
    const float* vp = g_v + (long)blk * 1568;
    for (int idx = tid; idx < 1568; idx += 256) { ((float*)ksh)[idx] = kp[idx]; ((float*)vsh)[idx] = vp[idx]; }
    __syncthreads();

    int n0 = blockIdx.y * 256, n = n0 + tid;
    if (n < N_) {
        const __half* qp = q + ((long)b*N_ + n)*DIM + h*64 + br*32;
        uint64_t q2[16];
        #pragma unroll
        for (int v = 0; v < 4; v++) {
            uint4 t = *(const uint4*)(qp + v*8);
            const __half2* hp = (const __half2*)&t;
            #pragma unroll
            for (int k2 = 0; k2 < 4; k2++) {
                float2 f = __half22float2(hp[k2]);
                PACK2(q2[v*4 + k2], f.x, f.y);
            }
        }
        float p[49], m = -1e30f;
        #pragma unroll
        for (int j = 0; j < 49; j++) {
            uint64_t acc2 = 0;
            #pragma unroll
            for (int d = 0; d < 8; d++) {
                ulonglong2 kk = *(const ulonglong2*)&ksh[j][d*4];
                FMA2(acc2, q2[d*2], kk.x);
                FMA2(acc2, q2[d*2+1], kk.y);
            }
            float lo, hi; UNPACK2(lo, hi, acc2);
            p[j] = lo + hi; m = fmaxf(m, p[j]);
        }
        float sum = 0.f;
        #pragma unroll
        for (int j = 0; j < 49; j++) { p[j] = __expf(p[j] - m); sum += p[j]; }
        float inv = 1.f / sum;
        uint64_t o2[16];
        #pragma unroll
        for (int d = 0; d < 16; d++) o2[d] = 0;
        #pragma unroll
        for (int j = 0; j < 49; j++) {
            uint64_t pj2; PACK2(pj2, p[j], p[j]);
            #pragma unroll
            for (int d = 0; d < 8; d++) {
                ulonglong2 vv = *(const ulonglong2*)&vsh[j][d*4];
                FMA2(o2[d*2], pj2, vv.x);
                FMA2(o2[d*2+1], pj2, vv.y);
            }
        }
        #pragma unroll
        for (int d = 0; d < 16; d++) {
            float lo, hi; UNPACK2(lo, hi, o2[d]);
            osh[tid][d*2]   = lo * inv;
            osh[tid][d*2+1] = hi * inv;
        }
    }
    __syncthreads();
    int off = br * SD + h * S_;
    for (int idx = tid; idx < 256*16; idx += 256) {
        int qq = idx >> 4, dp = (idx & 15) * 2;
        int nn = n0 + qq;
        if (nn < N_) {
            long o = ((long)b*N_ + nn)*DIM + off + dp;
            *(__half2*)(a16 + o) = __floats2half2_rn(osh[qq][dp], osh[qq][dp+1]);
        }
    }
}

// ---------------- launch ----------------
extern "C" void kernel_launch(void* const* d_in, const int* in_sizes, int n_in,
                              void* d_out, int out_size) {
    const float* x       = (const float*)d_in[0];
    const float* q_w     = (const float*)d_in[3];
    const float* kv_dw_w = (const float*)d_in[4];
    const float* kv_dw_b = (const float*)d_in[5];
    const float* kv_pw_w = (const float*)d_in[6];
    const float* kv_pw_b = (const float*)d_in[7];
    const float* fc_w0   = (const float*)d_in[8];
    const float* fc_w1   = (const float*)d_in[9];
    const float* sg_w0   = (const float*)d_in[10];
    const float* sg_w1   = (const float*)d_in[11];
    const float* lw0     = (const float*)d_in[12];
    const float* lb0     = (const float*)d_in[13];
    const float* lw1     = (const float*)d_in[14];
    const float* lb1     = (const float*)d_in[15];
    const float* proj_w  = (const float*)d_in[16];
    const float* proj_b  = (const float*)d_in[17];
    float* out = (float*)d_out;

    __half *x16, *d116, *a316, *q16, *w16;
    cudaGetSymbolAddress((void**)&x16, g_x16);
    cudaGetSymbolAddress((void**)&d116, g_d116);
    cudaGetSymbolAddress((void**)&a316, g_a316);
    cudaGetSymbolAddress((void**)&q16, g_q16);
    cudaGetSymbolAddress((void**)&w16, g_w16);

    cudaFuncSetAttribute(gemm_dual, cudaFuncAttributeMaxDynamicSharedMemorySize, GSMEM);

    wsplit3_kernel<<<dim3(DIM*DIM/4/256, 3), 256>>>(q_w, kv_pw_w, proj_w, w16);
    dwconv_kernel<<<BN/8, 128>>>(x, kv_dw_w, kv_dw_b, d116, x16);

    GemmArgs kvA { d116, w16 + DIM*DIM,   kv_pw_b, nullptr, nullptr, 2 };
    GemmArgs qA  { x16,  w16,             nullptr, nullptr, q16,     1 };
    GemmArgs pA  { a316, w16 + 2*DIM*DIM, proj_b,  out,     nullptr, 0 };

    gemm_dual<<<dim3(BN/128, DIM/128, 2), 256, GSMEM>>>(kvA, qA);
    prep_kernel<<<256, 256>>>(fc_w0, fc_w1, sg_w0, sg_w1, lw0, lb0, lw1, lb1);
    attn_kernel<<<dim3(256, (N_+255)/256), 256>>>(q16, a316);
    gemm_dual<<<dim3(BN/128, DIM/128, 1), 256, GSMEM>>>(pA, pA);
}

// round 17
// speedup vs baseline: 1.5443x; 1.2955x over previous
#include <cuda_runtime.h>
#include <cuda_fp16.h>
#include <cstdint>

#define B_    16
#define N_    3136
#define DIM   512
#define HEADS 8
#define HW    56
#define SD    256
#define S_    32
#define BN    (B_ * N_)
#define ELEMS ((long)BN * DIM)

// ---------------- scratch ----------------
__device__ __half g_x16[ELEMS];
__device__ __half g_d116[ELEMS];
__device__ __half g_a316[ELEMS];
__device__ __half g_q16[ELEMS];
__device__ __half g_w16[3][DIM * DIM];
__device__ float g_half[B_][32][N_];
__device__ float g_k[2 * B_ * HEADS * 49 * S_];
__device__ float g_v[2 * B_ * HEADS * 49 * S_];

// ---------------- helpers ----------------
__device__ __forceinline__ uint32_t smem_u32(const void* p) {
    uint32_t a;
    asm("{ .reg .u64 t; cvta.to.shared.u64 t, %1; cvt.u32.u64 %0, t; }" : "=r"(a) : "l"(p));
    return a;
}
__device__ __forceinline__ void cp16(uint32_t d, const void* g) {
    asm volatile("cp.async.cg.shared.global [%0], [%1], 16;" :: "r"(d), "l"(g));
}
#define CP_COMMIT() asm volatile("cp.async.commit_group;" ::: "memory")
#define CP_WAIT(n)  asm volatile("cp.async.wait_group %0;" :: "n"(n) : "memory")

#define LDSM_X4(r, a) \
    asm volatile("ldmatrix.sync.aligned.m8n8.x4.shared.b16 {%0,%1,%2,%3}, [%4];" \
        : "=r"((r)[0]), "=r"((r)[1]), "=r"((r)[2]), "=r"((r)[3]) : "r"(a))
#define LDSM_X2(r, a) \
    asm volatile("ldmatrix.sync.aligned.m8n8.x2.shared.b16 {%0,%1}, [%2];" \
        : "=r"((r)[0]), "=r"((r)[1]) : "r"(a))
#define MMA16816F16(c, a, b) \
    asm volatile("mma.sync.aligned.m16n8k16.row.col.f32.f16.f16.f32 " \
        "{%0,%1,%2,%3},{%4,%5,%6,%7},{%8,%9},{%0,%1,%2,%3};" \
        : "+f"((c)[0]), "+f"((c)[1]), "+f"((c)[2]), "+f"((c)[3]) \
        : "r"((a)[0]), "r"((a)[1]), "r"((a)[2]), "r"((a)[3]), "r"((b)[0]), "r"((b)[1]))

__device__ __forceinline__ void store_h4(float4 v, __half* dst) {
    __half2* d = (__half2*)dst;
    d[0] = __floats2half2_rn(v.x, v.y);
    d[1] = __floats2half2_rn(v.z, v.w);
}

// ---------------- weight conversion ----------------
__global__ void wsplit3_kernel(const float* __restrict__ s0, const float* __restrict__ s1,
                               const float* __restrict__ s2, __half* __restrict__ out) {
    int w = blockIdx.y;
    const float* src = w == 0 ? s0 : (w == 1 ? s1 : s2);
    long i = (long)blockIdx.x * blockDim.x + threadIdx.x;
    float4 v = ((const float4*)src)[i];
    store_h4(v, out + (long)w * DIM * DIM + i * 4);
}

// ---------------- 3x3 depthwise conv + fused x convert ----------------
__global__ void __launch_bounds__(128)
dwconv_kernel(const float* __restrict__ x, const float* __restrict__ w,
              const float* __restrict__ bias,
              __half* __restrict__ o16, __half* __restrict__ x16) {
    int p0 = blockIdx.x * 8;
    int c4 = threadIdx.x * 4;
    float wr[9][4];
    #pragma unroll
    for (int t = 0; t < 9; t++)
        #pragma unroll
        for (int cc = 0; cc < 4; cc++) wr[t][cc] = w[(c4 + cc) * 9 + t];
    float4 b4 = *(const float4*)(bias + c4);

    #pragma unroll
    for (int pp = 0; pp < 8; pp++) {
        int p = p0 + pp;
        int b = p / N_, pix = p - b * N_;
        int hy = pix / HW, hx = pix - hy * HW;
        float4 acc = b4, xc = make_float4(0.f, 0.f, 0.f, 0.f);
        #pragma unroll
        for (int dy = 0; dy < 3; dy++) {
            int yy = hy + dy - 1;
            if (yy < 0 || yy >= HW) continue;
            #pragma unroll
            for (int dx = 0; dx < 3; dx++) {
                int xx = hx + dx - 1;
                if (xx < 0 || xx >= HW) continue;
                float4 v = *(const float4*)(x + ((long)b * N_ + yy * HW + xx) * DIM + c4);
                if (dy == 1 && dx == 1) xc = v;
                int t = dy * 3 + dx;
                acc.x += wr[t][0] * v.x; acc.y += wr[t][1] * v.y;
                acc.z += wr[t][2] * v.z; acc.w += wr[t][3] * v.w;
            }
        }
        long off = (long)p * DIM + c4;
        store_h4(acc, o16 + off);
        store_h4(xc,  x16 + off);
    }
}

// ---------------------------------------------------------------------------
// fp16 mma.sync GEMM — tile 128x128, 256 thr, 2 CTA/SM, K-chunk 64, 2-stage
// (byte-identical to R16)
// ---------------------------------------------------------------------------
#define STAGE_B  36864
#define GSMEM    (2 * STAGE_B)

struct GemmArgs {
    const __half *A, *W;
    const float* bias;
    float* C;
    __half* C16;
    int mode;
};

__global__ void __launch_bounds__(256, 2)
gemm_dual(GemmArgs a0, GemmArgs a1) {
    const GemmArgs& g = blockIdx.z ? a1 : a0;
    const __half* __restrict__ A = g.A;
    const __half* __restrict__ W = g.W;
    const float* bias = g.bias;

    extern __shared__ char smem[];
    uint32_t sb = smem_u32(smem);
    const int tid = threadIdx.x, lane = tid & 31, wid = tid >> 5;
    const int wm = wid & 1, wn = wid >> 1;
    const long m0 = (long)blockIdx.x * 128;
    const int n0 = blockIdx.y * 128;

    auto load_chunk = [&](int ck, int st) {
        uint32_t base = sb + st * STAGE_B;
        #pragma unroll
        for (int it = 0; it < 8; it++) {
            int idx = tid + it * 256;
            int arr = idx >> 10;
            int loc = idx & 1023;
            int r = loc >> 3, seg = loc & 7;
            const __half* gp = arr == 0
                ? A + (m0 + r) * DIM + ck * 64 + seg * 8
                : W + (long)(n0 + r) * DIM + ck * 64 + seg * 8;
            cp16(base + arr * 18432 + r * 144 + seg * 16, gp);
        }
        CP_COMMIT();
    };

    float acc[4][4][4];
    #pragma unroll
    for (int i = 0; i < 4; i++)
        #pragma unroll
        for (int j = 0; j < 4; j++)
            #pragma unroll
            for (int r = 0; r < 4; r++) acc[i][j][r] = 0.f;

    load_chunk(0, 0);

    const int arow = lane & 15;
    const int acolB = (lane >> 4) ? 16 : 0;
    const int brow8 = (lane & 7) + (((lane >> 4) & 1) << 3);
    const int bcolB = ((lane >> 3) & 1) ? 16 : 0;

    for (int c = 0; c < 8; c++) {
        if (c + 1 < 8) { load_chunk(c + 1, (c + 1) & 1); CP_WAIT(1); }
        else           { CP_WAIT(0); }
        __syncthreads();
        uint32_t base = sb + (c & 1) * STAGE_B;
        #pragma unroll
        for (int ks = 0; ks < 4; ks++) {
            const int kb = ks * 32;
            uint32_t ah[4][4];
            #pragma unroll
            for (int i = 0; i < 4; i++) {
                uint32_t addr = base + (wm * 64 + i * 16 + arow) * 144 + kb + acolB;
                LDSM_X4(ah[i], addr);
            }
            #pragma unroll
            for (int jj = 0; jj < 2; jj++) {
                uint32_t baddr = base + 18432
                    + (wn * 32 + jj * 16 + brow8) * 144 + kb + bcolB;
                uint32_t bw[4];
                LDSM_X4(bw, baddr);
                #pragma unroll
                for (int i = 0; i < 4; i++) {
                    MMA16816F16(acc[i][2*jj],   ah[i], bw);
                    MMA16816F16(acc[i][2*jj+1], ah[i], bw + 2);
                }
            }
        }
        __syncthreads();
    }

    if (g.mode == 2) {
        #pragma unroll
        for (int i = 0; i < 4; i++) {
            float gA0 = 0.f, gA8 = 0.f, gB0 = 0.f, gB8 = 0.f;
            #pragma unroll
            for (int j = 0; j < 4; j++) {
                int col = n0 + wn * 32 + j * 8 + (lane & 3) * 2;
                float b0 = bias[col], b1 = bias[col + 1];
                float s0 = acc[i][j][0] + b0 + acc[i][j][1] + b1;
                float s8 = acc[i][j][2] + b0 + acc[i][j][3] + b1;
                if (j < 2) { gA0 += s0; gA8 += s8; }
                else       { gB0 += s0; gB8 += s8; }
            }
            #pragma unroll
            for (int d = 1; d <= 2; d <<= 1) {
                gA0 += __shfl_xor_sync(0xffffffffu, gA0, d);
                gA8 += __shfl_xor_sync(0xffffffffu, gA8, d);
                gB0 += __shfl_xor_sync(0xffffffffu, gB0, d);
                gB8 += __shfl_xor_sync(0xffffffffu, gB8, d);
            }
            if ((lane & 3) == 0) {
                int g0 = (n0 + wn * 32) >> 4, g1 = g0 + 1;
                long m = m0 + wm * 64 + i * 16 + (lane >> 2);
                int bb = (int)(m / N_), pix = (int)(m - (long)bb * N_);
                g_half[bb][g0][pix] = gA0;
                g_half[bb][g1][pix] = gB0;
                m += 8; bb = (int)(m / N_); pix = (int)(m - (long)bb * N_);
                g_half[bb][g0][pix] = gA8;
                g_half[bb][g1][pix] = gB8;
            }
        }
    } else if (g.mode == 1) {
        __half* C16 = g.C16;
        #pragma unroll
        for (int i = 0; i < 4; i++) {
            long r0 = m0 + wm * 64 + i * 16 + (lane >> 2);
            #pragma unroll
            for (int j = 0; j < 4; j++) {
                int col = n0 + wn * 32 + j * 8 + (lane & 3) * 2;
                *(__half2*)(C16 + r0 * DIM + col) =
                    __floats2half2_rn(acc[i][j][0], acc[i][j][1]);
                *(__half2*)(C16 + (r0 + 8) * DIM + col) =
                    __floats2half2_rn(acc[i][j][2], acc[i][j][3]);
            }
        }
    } else {
        float* C = g.C;
        #pragma unroll
        for (int i = 0; i < 4; i++) {
            long r0 = m0 + wm * 64 + i * 16 + (lane >> 2);
            #pragma unroll
            for (int j = 0; j < 4; j++) {
                int col = n0 + wn * 32 + j * 8 + (lane & 3) * 2;
                float b0 = bias ? bias[col] : 0.f, b1 = bias ? bias[col + 1] : 0.f;
                float2 v0 = { acc[i][j][0] + b0, acc[i][j][1] + b1 };
                float2 v1 = { acc[i][j][2] + b0, acc[i][j][3] + b1 };
                *(float2*)(C + r0 * DIM + col) = v0;
                *(float2*)(C + (r0 + 8) * DIM + col) = v1;
            }
        }
    }
}

// ---------------- prep ----------------
__global__ void prep_kernel(const float* __restrict__ fc0, const float* __restrict__ fc1,
                            const float* __restrict__ sg0, const float* __restrict__ sg1,
                            const float* __restrict__ lw0, const float* __restrict__ lb0,
                            const float* __restrict__ lw1, const float* __restrict__ lb1) {
    int blk = blockIdx.x;
    int br = blk >> 7, bh = blk & 127, b = bh >> 3, h = bh & 7;
    int tid = threadIdx.x;
    __shared__ float pooled[49][32], tmp[49][32], vsh[49][33];

    for (int idx = tid; idx < 49*32; idx += 256) {
        int w = idx >> 5, s = idx & 31;
        int ky = w / 7, kx = w - ky * 7;
        float sum;
        if (br == 0) {
            int ll0 = 2*s, ll1 = 2*s + 1;
            int p0 = ((ll0>>3)*7 + ky)*HW + (ll0&7)*7 + kx;
            int p1 = ((ll1>>3)*7 + ky)*HW + (ll1&7)*7 + kx;
            sum = (g_half[b][2*h][p0] + g_half[b][2*h+1][p0]
                 + g_half[b][2*h][p1] + g_half[b][2*h+1][p1]) * (1.f/64.f);
        } else {
            int ll = s >> 1;
            int p = ((ll>>2)*13 + ky*2)*HW + (ll&3)*13 + kx*2;
            sum = g_half[b][16 + 2*h + (s&1)][p] * (1.f/16.f);
        }
        pooled[w][s] = sum;
    }
    __syncthreads();
    const float* fc = br ? fc1 : fc0;
    for (int idx = tid; idx < 49*32; idx += 256) {
        int w = idx >> 5, t = idx & 31;
        float sum = 0.f;
        #pragma unroll
        for (int s = 0; s < 32; s++) sum += pooled[w][s] * fc[t*32+s];
        tmp[w][t] = sum;
    }
    __syncthreads();
    const float* sg = br ? sg1 : sg0;
    const float kscale = 0.17677669529663689f;
    for (int idx = tid; idx < 49*64; idx += 256) {
        int w = idx >> 6, j = idx & 63;
        float sum = 0.f;
        #pragma unroll
        for (int t = 0; t < 32; t++) sum += tmp[w][t] * sg[j*32+t];
        if (j < 32) g_k[(long)blk*1568 + w*32 + j] = sum * kscale;
        else        vsh[w][j-32] = sum;
    }
    __syncthreads();
    const float* lw = br ? lw1 : lw0;
    const float* lb = br ? lb1 : lb0;
    for (int idx = tid; idx < 49*32; idx += 256) {
        int w = idx >> 5, s = idx & 31;
        int wy = w / 7, wx = w - wy * 7, ch = h*S_ + s;
        float acc = vsh[w][s] + lb[ch];
        #pragma unroll
        for (int dy = 0; dy < 3; dy++) {
            int yy = wy + dy - 1;
            if (yy < 0 || yy >= 7) continue;
            #pragma unroll
            for (int dx = 0; dx < 3; dx++) {
                int xx = wx + dx - 1;
                if (xx < 0 || xx >= 7) continue;
                acc += lw[ch*9 + dy*3 + dx] * vsh[yy*7+xx][s];
            }
        }
        g_v[(long)blk*1568 + w*32 + s] = acc;
    }
}

// ---------------------------------------------------------------------------
// attention via mma.sync: per (branch,b,h) x 128-query tile, 4 warps.
// S = Q K^T (n padded 49->64, masked), softmax in regs (quad shfl),
// P stays in A-fragment layout, O = P V^T.
// ---------------------------------------------------------------------------
__global__ void __launch_bounds__(128)
attn_kernel(const __half* __restrict__ q, __half* __restrict__ a16) {
    __shared__ __half qsh[128][40];   // 80B row stride
    __shared__ __half ksh[64][40];    // rows j (n), cols d (k); pad rows zero
    __shared__ __half vsh[32][72];    // rows d (n), cols j (k); 144B stride

    int blk = blockIdx.x;
    int br = blk >> 7, bh = blk & 127, b = bh >> 3, h = bh & 7;
    int tid = threadIdx.x, lane = tid & 31, wid = tid >> 5;
    int n0 = blockIdx.y * 128;

    // zero pads (full clear is cheap: 2432+1152 words)
    for (int i = tid; i < 64*20; i += 128) ((uint32_t*)ksh)[i] = 0;
    for (int i = tid; i < 32*36; i += 128) ((uint32_t*)vsh)[i] = 0;

    // Q tile via cp.async (row = query pixel, 32 halves = 4x16B), clamp OOB rows
    {
        int r = tid;                     // 128 rows, 1 per thread
        int pix = n0 + r; if (pix >= N_) pix = N_ - 1;
        const __half* qp = q + ((long)b*N_ + pix)*DIM + h*64 + br*32;
        uint32_t dst = smem_u32(&qsh[r][0]);
        #pragma unroll
        for (int s = 0; s < 4; s++) cp16(dst + s*16, qp + s*8);
        CP_COMMIT();
    }
    __syncthreads();   // pads visible before fill

    const float* kp = g_k + (long)blk * 1568;
    const float* vp = g_v + (long)blk * 1568;
    for (int idx = tid; idx < 1568; idx += 128) {
        int j = idx >> 5, d = idx & 31;
        ksh[j][d] = __float2half(kp[idx]);
        vsh[d][j] = __float2half(vp[idx]);
    }
    CP_WAIT(0);
    __syncthreads();

    const int arow = lane & 15;
    const int acolB = (lane >> 4) ? 16 : 0;
    const int brow = lane & 7;
    const int bcolB = ((lane >> 3) & 1) ? 16 : 0;

    // ---- S = Q K^T : 2 m-tiles x 8 n-tiles x 2 k-chunks ----
    float S[2][8][4];
    #pragma unroll
    for (int mt = 0; mt < 2; mt++)
        #pragma unroll
        for (int nt = 0; nt < 8; nt++)
            #pragma unroll
            for (int r = 0; r < 4; r++) S[mt][nt][r] = 0.f;

    #pragma unroll
    for (int kc = 0; kc < 2; kc++) {
        const int kb = kc * 32;
        uint32_t bw[8][2];
        #pragma unroll
        for (int nt = 0; nt < 8; nt++)
            LDSM_X2(bw[nt], smem_u32(&ksh[0][0]) + (nt*8 + brow)*80 + kb + bcolB);
        #pragma unroll
        for (int mt = 0; mt < 2; mt++) {
            uint32_t ah[4];
            LDSM_X4(ah, smem_u32(&qsh[0][0]) + (wid*32 + mt*16 + arow)*80 + kb + acolB);
            #pragma unroll
            for (int nt = 0; nt < 8; nt++)
                MMA16816F16(S[mt][nt], ah, bw[nt]);
        }
    }

    // ---- softmax (rows r and r+8 per thread), P packed as A-fragments ----
    uint32_t phA[2][8], phB[2][8];     // half2: row r / row r+8
    float inv0[2], inv8[2];
    const int c0b = (lane & 3) * 2;
    #pragma unroll
    for (int mt = 0; mt < 2; mt++) {
        float mr = -1e30f, mr8 = -1e30f;
        #pragma unroll
        for (int nt = 0; nt < 7; nt++) {
            int c0 = nt*8 + c0b;
            if (c0 < 49)     { mr = fmaxf(mr, S[mt][nt][0]); mr8 = fmaxf(mr8, S[mt][nt][2]); }
            if (c0 + 1 < 49) { mr = fmaxf(mr, S[mt][nt][1]); mr8 = fmaxf(mr8, S[mt][nt][3]); }
        }
        #pragma unroll
        for (int d = 1; d <= 2; d <<= 1) {
            mr  = fmaxf(mr,  __shfl_xor_sync(0xffffffffu, mr,  d));
            mr8 = fmaxf(mr8, __shfl_xor_sync(0xffffffffu, mr8, d));
        }
        float sr = 0.f, sr8 = 0.f;
        #pragma unroll
        for (int nt = 0; nt < 8; nt++) {
            int c0 = nt*8 + c0b;
            float p0 = (c0 < 49)     ? __expf(S[mt][nt][0] - mr)  : 0.f;
            float p1 = (c0 + 1 < 49) ? __expf(S[mt][nt][1] - mr)  : 0.f;
            float p2 = (c0 < 49)     ? __expf(S[mt][nt][2] - mr8) : 0.f;
            float p3 = (c0 + 1 < 49) ? __expf(S[mt][nt][3] - mr8) : 0.f;
            sr += p0 + p1; sr8 += p2 + p3;
            __half2 hA = __floats2half2_rn(p0, p1);
            __half2 hB = __floats2half2_rn(p2, p3);
            phA[mt][nt] = *(uint32_t*)&hA;
            phB[mt][nt] = *(uint32_t*)&hB;
        }
        #pragma unroll
        for (int d = 1; d <= 2; d <<= 1) {
            sr  += __shfl_xor_sync(0xffffffffu, sr,  d);
            sr8 += __shfl_xor_sync(0xffffffffu, sr8, d);
        }
        inv0[mt] = 1.f / sr; inv8[mt] = 1.f / sr8;
    }

    // ---- O = P V^T : 2 m-tiles x 4 d-tiles x 4 k-chunks ----
    float O[2][4][4];
    #pragma unroll
    for (int mt = 0; mt < 2; mt++)
        #pragma unroll
        for (int dt = 0; dt < 4; dt++)
            #pragma unroll
            for (int r = 0; r < 4; r++) O[mt][dt][r] = 0.f;

    #pragma unroll
    for (int kc = 0; kc < 4; kc++) {
        const int kb = kc * 32;
        uint32_t bw[4][2];
        #pragma unroll
        for (int dt = 0; dt < 4; dt++)
            LDSM_X2(bw[dt], smem_u32(&vsh[0][0]) + (dt*8 + brow)*144 + kb + bcolB);
        #pragma unroll
        for (int mt = 0; mt < 2; mt++) {
            uint32_t aF[4] = { phA[mt][2*kc], phB[mt][2*kc],
                               phA[mt][2*kc+1], phB[mt][2*kc+1] };
            #pragma unroll
            for (int dt = 0; dt < 4; dt++)
                MMA16816F16(O[mt][dt], aF, bw[dt]);
        }
    }

    // ---- write O (fp16), normalized ----
    int off = br * SD + h * S_;
    #pragma unroll
    for (int mt = 0; mt < 2; mt++) {
        int r = wid*32 + mt*16 + (lane >> 2);
        int pix0 = n0 + r, pix8 = pix0 + 8;
        #pragma unroll
        for (int dt = 0; dt < 4; dt++) {
            int d = dt*8 + c0b;
            if (pix0 < N_) {
                __half2 v = __floats2half2_rn(O[mt][dt][0]*inv0[mt], O[mt][dt][1]*inv0[mt]);
                *(__half2*)(a16 + ((long)b*N_ + pix0)*DIM + off + d) = v;
            }
            if (pix8 < N_) {
                __half2 v = __floats2half2_rn(O[mt][dt][2]*inv8[mt], O[mt][dt][3]*inv8[mt]);
                *(__half2*)(a16 + ((long)b*N_ + pix8)*DIM + off + d) = v;
            }
        }
    }
}

// ---------------- launch ----------------
extern "C" void kernel_launch(void* const* d_in, const int* in_sizes, int n_in,
                              void* d_out, int out_size) {
    const float* x       = (const float*)d_in[0];
    const float* q_w     = (const float*)d_in[3];
    const float* kv_dw_w = (const float*)d_in[4];
    const float* kv_dw_b = (const float*)d_in[5];
    const float* kv_pw_w = (const float*)d_in[6];
    const float* kv_pw_b = (const float*)d_in[7];
    const float* fc_w0   = (const float*)d_in[8];
    const float* fc_w1   = (const float*)d_in[9];
    const float* sg_w0   = (const float*)d_in[10];
    const float* sg_w1   = (const float*)d_in[11];
    const float* lw0     = (const float*)d_in[12];
    const float* lb0     = (const float*)d_in[13];
    const float* lw1     = (const float*)d_in[14];
    const float* lb1     = (const float*)d_in[15];
    const float* proj_w  = (const float*)d_in[16];
    const float* proj_b  = (const float*)d_in[17];
    float* out = (float*)d_out;

    __half *x16, *d116, *a316, *q16, *w16;
    cudaGetSymbolAddress((void**)&x16, g_x16);
    cudaGetSymbolAddress((void**)&d116, g_d116);
    cudaGetSymbolAddress((void**)&a316, g_a316);
    cudaGetSymbolAddress((void**)&q16, g_q16);
    cudaGetSymbolAddress((void**)&w16, g_w16);

    cudaFuncSetAttribute(gemm_dual, cudaFuncAttributeMaxDynamicSharedMemorySize, GSMEM);

    wsplit3_kernel<<<dim3(DIM*DIM/4/256, 3), 256>>>(q_w, kv_pw_w, proj_w, w16);
    dwconv_kernel<<<BN/8, 128>>>(x, kv_dw_w, kv_dw_b, d116, x16);

    GemmArgs kvA { d116, w16 + DIM*DIM,   kv_pw_b, nullptr, nullptr, 2 };
    GemmArgs qA  { x16,  w16,             nullptr, nullptr, q16,     1 };
    GemmArgs pA  { a316, w16 + 2*DIM*DIM, proj_b,  out,     nullptr, 0 };

    gemm_dual<<<dim3(BN/128, DIM/128, 2), 256, GSMEM>>>(kvA, qA);
    prep_kernel<<<256, 256>>>(fc_w0, fc_w1, sg_w0, sg_w1, lw0, lb0, lw1, lb1);
    attn_kernel<<<dim3(256, (N_ + 127) / 128), 128>>>(q16, a316);
    gemm_dual<<<dim3(BN/128, DIM/128, 1), 256, GSMEM>>>(pA, pA);
}